// round 4
// baseline (speedup 1.0000x reference)
#include <cuda_runtime.h>
#include <stdint.h>

#define NPIX  200704        // 64 * 56 * 56
#define HW    3136          // 56 * 56
#define WID   56
#define NTHR4 (NPIX / 4)    // 50176 threads, 4 pixels each

// Intermediate: 32 sign bits (channels of h) per pixel, layout [b*HW + s]
__device__ uint32_t g_a[NPIX];

// Packed weights + folded BN params
__device__ unsigned long long g_w1b[32];
__device__ float g_inv1[32], g_sh1[32];
__device__ uint32_t g_w2p[96][3];
__device__ float g_inv2[96], g_sh2[96];
__device__ uint32_t g_w3p[96][3];
__device__ float g_inv3[96], g_sh3[96];
__device__ uint32_t g_w4p[64];
__device__ float g_inv4[64], g_sh4[64];

// ---------------------------------------------------------------------------
// Prep: pack sign bits of weights, fold BN into (inv, shift)
// ---------------------------------------------------------------------------
__global__ void kPrep(const float* __restrict__ w1, const float* __restrict__ g1,
                      const float* __restrict__ b1, const float* __restrict__ m1,
                      const float* __restrict__ v1,
                      const float* __restrict__ w2, const float* __restrict__ g2,
                      const float* __restrict__ b2, const float* __restrict__ m2,
                      const float* __restrict__ v2,
                      const float* __restrict__ w3, const float* __restrict__ g3,
                      const float* __restrict__ b3, const float* __restrict__ m3,
                      const float* __restrict__ v3,
                      const float* __restrict__ w4, const float* __restrict__ g4,
                      const float* __restrict__ b4, const float* __restrict__ m4,
                      const float* __restrict__ v4)
{
    int t = threadIdx.x;   // 96 threads
    if (t < 32) {
        unsigned long long bits = 0;
        for (int c = 0; c < 64; c++)
            if (w1[t * 64 + c] > 0.0f) bits |= 1ull << c;
        g_w1b[t] = bits;
        float inv = g1[t] * rsqrtf(v1[t] + 1e-5f);
        g_inv1[t] = inv;
        g_sh1[t]  = b1[t] - m1[t] * inv;
    }
    if (t < 96) {
        for (int k = 0; k < 3; k++) {
            uint32_t b2b = 0, b3b = 0;
            for (int c = 0; c < 32; c++) {
                if (w2[(t * 32 + c) * 3 + k] > 0.0f) b2b |= 1u << c;
                if (w3[(t * 32 + c) * 3 + k] > 0.0f) b3b |= 1u << c;
            }
            g_w2p[t][k] = b2b;
            g_w3p[t][k] = b3b;
        }
        float inv = g2[t] * rsqrtf(v2[t] + 1e-5f);
        g_inv2[t] = inv; g_sh2[t] = b2[t] - m2[t] * inv;
        inv = g3[t] * rsqrtf(v3[t] + 1e-5f);
        g_inv3[t] = inv; g_sh3[t] = b3[t] - m3[t] * inv;
    }
    if (t < 64) {
        uint32_t bits = 0;
        for (int c = 0; c < 32; c++)
            if (w4[t * 32 + c] > 0.0f) bits |= 1u << c;
        g_w4p[t] = bits;
        float inv = g4[t] * rsqrtf(v4[t] + 1e-5f);
        g_inv4[t] = inv; g_sh4[t] = b4[t] - m4[t] * inv;
    }
}

// ---------------------------------------------------------------------------
// Kernel A: x [N=64, C=64, 56, 56] (NCHW) -> g_a sign masks
// Each thread: 4 consecutive pixels within one batch image (float4 per channel).
// ---------------------------------------------------------------------------
__global__ __launch_bounds__(256) void kA(const float* __restrict__ x)
{
    __shared__ unsigned long long sw1[32];
    __shared__ float sinv[32], ssh[32];
    if (threadIdx.x < 32) {
        sw1[threadIdx.x]  = g_w1b[threadIdx.x];
        sinv[threadIdx.x] = g_inv1[threadIdx.x];
        ssh[threadIdx.x]  = g_sh1[threadIdx.x];
    }
    __syncthreads();

    int t = blockIdx.x * 256 + threadIdx.x;
    if (t >= NTHR4) return;
    int p = t * 4;                 // global pixel index = b*HW + s
    int b = p / HW;
    int s = p - b * HW;            // multiple of 4 (HW % 4 == 0)
    const float* xb = x + (size_t)b * 64 * HW + s;

    unsigned long long xb0 = 0, xb1 = 0, xb2 = 0, xb3 = 0;
#pragma unroll
    for (int c = 0; c < 64; c++) {
        float4 v = __ldg((const float4*)(xb + (size_t)c * HW));
        unsigned long long m = 1ull << c;
        if (v.x > 0.0f) xb0 |= m;
        if (v.y > 0.0f) xb1 |= m;
        if (v.z > 0.0f) xb2 |= m;
        if (v.w > 0.0f) xb3 |= m;
    }

    uint32_t a0 = 0, a1 = 0, a2 = 0, a3 = 0;
#pragma unroll
    for (int o = 0; o < 32; o++) {
        unsigned long long wb = sw1[o];
        float inv = sinv[o], sh = ssh[o];
        uint32_t m = 1u << o;
        int d0 = 64 - 2 * __popcll(xb0 ^ wb);
        int d1 = 64 - 2 * __popcll(xb1 ^ wb);
        int d2 = 64 - 2 * __popcll(xb2 ^ wb);
        int d3 = 64 - 2 * __popcll(xb3 ^ wb);
        if (fmaf((float)d0, inv, sh) > 0.0f) a0 |= m;
        if (fmaf((float)d1, inv, sh) > 0.0f) a1 |= m;
        if (fmaf((float)d2, inv, sh) > 0.0f) a2 |= m;
        if (fmaf((float)d3, inv, sh) > 0.0f) a3 |= m;
    }
    *(uint4*)(g_a + p) = make_uint4(a0, a1, a2, a3);
}

// ---------------------------------------------------------------------------
// Kernel B: g_a -> output [64,256,56,56]
// Each thread: 4 consecutive pixels along W, all 256 out channels.
// ---------------------------------------------------------------------------
__global__ __launch_bounds__(128) void kB(float* __restrict__ out)
{
    __shared__ uint32_t sw2[96 * 3], sw3[96 * 3], sw4[64];
    __shared__ float si2[96], ss2[96], si3[96], ss3[96], si4[64], ss4[64];

    for (int i = threadIdx.x; i < 96; i += 128) {
        sw2[3 * i]     = g_w2p[i][0];
        sw2[3 * i + 1] = g_w2p[i][1];
        sw2[3 * i + 2] = g_w2p[i][2];
        sw3[3 * i]     = g_w3p[i][0];
        sw3[3 * i + 1] = g_w3p[i][1];
        sw3[3 * i + 2] = g_w3p[i][2];
        si2[i] = g_inv2[i]; ss2[i] = g_sh2[i];
        si3[i] = g_inv3[i]; ss3[i] = g_sh3[i];
    }
    for (int i = threadIdx.x; i < 64; i += 128) {
        sw4[i] = g_w4p[i]; si4[i] = g_inv4[i]; ss4[i] = g_sh4[i];
    }
    __syncthreads();

    int q  = blockIdx.x * 128 + threadIdx.x;   // 0..50175
    int xq = q % 14;
    int r  = q / 14;
    int y  = r % 56;
    int bb = r / 56;
    int base = bb * HW + y * WID;
    int x0   = xq * 4;

    uint4 A0 = *(const uint4*)&g_a[base + x0];
    uint4 Am = make_uint4(0, 0, 0, 0), Ap = make_uint4(0, 0, 0, 0);
    if (y > 0)  Am = *(const uint4*)&g_a[base - WID + x0];
    if (y < 55) Ap = *(const uint4*)&g_a[base + WID + x0];
    uint32_t hL = (xq > 0)  ? g_a[base + x0 - 1] : 0u;
    uint32_t hR = (xq < 13) ? g_a[base + x0 + 4] : 0u;

    int pc0 = __popc(A0.x), pc1 = __popc(A0.y), pc2 = __popc(A0.z), pc3 = __popc(A0.w);
    int pv0 = __popc(Am.x) + pc0 + __popc(Ap.x);
    int pv1 = __popc(Am.y) + pc1 + __popc(Ap.y);
    int pv2 = __popc(Am.z) + pc2 + __popc(Ap.z);
    int pv3 = __popc(Am.w) + pc3 + __popc(Ap.w);
    int pL = __popc(hL), pR = __popc(hR);
    int ph0 = pL  + pc0 + pc1;
    int ph1 = pc0 + pc1 + pc2;
    int ph2 = pc1 + pc2 + pc3;
    int ph3 = pc2 + pc3 + pR;

    float* o1 = out + (size_t)bb * 256 * HW + y * WID + x0;

    // Branch 1: 3x1 vertical conv (channels 0..95)
#pragma unroll 4
    for (int o = 0; o < 96; o++) {
        uint32_t w0 = sw2[3 * o], w1 = sw2[3 * o + 1], w2 = sw2[3 * o + 2];
        float inv = si2[o], sh = ss2[o];
        float4 rv;
        int d;
        d = 2 * (__popc(Am.x & w0) + __popc(A0.x & w1) + __popc(Ap.x & w2)) - pv0;
        rv.x = fmaxf(fmaf((float)d, inv, sh), 0.0f);
        d = 2 * (__popc(Am.y & w0) + __popc(A0.y & w1) + __popc(Ap.y & w2)) - pv1;
        rv.y = fmaxf(fmaf((float)d, inv, sh), 0.0f);
        d = 2 * (__popc(Am.z & w0) + __popc(A0.z & w1) + __popc(Ap.z & w2)) - pv2;
        rv.z = fmaxf(fmaf((float)d, inv, sh), 0.0f);
        d = 2 * (__popc(Am.w & w0) + __popc(A0.w & w1) + __popc(Ap.w & w2)) - pv3;
        rv.w = fmaxf(fmaf((float)d, inv, sh), 0.0f);
        *(float4*)(o1 + (size_t)o * HW) = rv;
    }

    // Branch 2: 1x3 horizontal conv (channels 96..191)
    float* o2 = o1 + (size_t)96 * HW;
#pragma unroll 4
    for (int o = 0; o < 96; o++) {
        uint32_t w0 = sw3[3 * o], w1 = sw3[3 * o + 1], w2 = sw3[3 * o + 2];
        float inv = si3[o], sh = ss3[o];
        float4 rv;
        int d;
        d = 2 * (__popc(hL   & w0) + __popc(A0.x & w1) + __popc(A0.y & w2)) - ph0;
        rv.x = fmaxf(fmaf((float)d, inv, sh), 0.0f);
        d = 2 * (__popc(A0.x & w0) + __popc(A0.y & w1) + __popc(A0.z & w2)) - ph1;
        rv.y = fmaxf(fmaf((float)d, inv, sh), 0.0f);
        d = 2 * (__popc(A0.y & w0) + __popc(A0.z & w1) + __popc(A0.w & w2)) - ph2;
        rv.z = fmaxf(fmaf((float)d, inv, sh), 0.0f);
        d = 2 * (__popc(A0.z & w0) + __popc(A0.w & w1) + __popc(hR   & w2)) - ph3;
        rv.w = fmaxf(fmaf((float)d, inv, sh), 0.0f);
        *(float4*)(o2 + (size_t)o * HW) = rv;
    }

    // Branch 3: 1x1 conv (channels 192..255)
    float* o3 = o1 + (size_t)192 * HW;
#pragma unroll 4
    for (int o = 0; o < 64; o++) {
        uint32_t w = sw4[o];
        float inv = si4[o], sh = ss4[o];
        float4 rv;
        rv.x = fmaxf(fmaf((float)(2 * __popc(A0.x & w) - pc0), inv, sh), 0.0f);
        rv.y = fmaxf(fmaf((float)(2 * __popc(A0.y & w) - pc1), inv, sh), 0.0f);
        rv.z = fmaxf(fmaf((float)(2 * __popc(A0.z & w) - pc2), inv, sh), 0.0f);
        rv.w = fmaxf(fmaf((float)(2 * __popc(A0.w & w) - pc3), inv, sh), 0.0f);
        *(float4*)(o3 + (size_t)o * HW) = rv;
    }
}

// ---------------------------------------------------------------------------
extern "C" void kernel_launch(void* const* d_in, const int* in_sizes, int n_in,
                              void* d_out, int out_size)
{
    const float* x = (const float*)d_in[0];
    kPrep<<<1, 96>>>((const float*)d_in[1],  (const float*)d_in[2],
                     (const float*)d_in[3],  (const float*)d_in[4],
                     (const float*)d_in[5],
                     (const float*)d_in[6],  (const float*)d_in[7],
                     (const float*)d_in[8],  (const float*)d_in[9],
                     (const float*)d_in[10],
                     (const float*)d_in[11], (const float*)d_in[12],
                     (const float*)d_in[13], (const float*)d_in[14],
                     (const float*)d_in[15],
                     (const float*)d_in[16], (const float*)d_in[17],
                     (const float*)d_in[18], (const float*)d_in[19],
                     (const float*)d_in[20]);
    kA<<<NTHR4 / 256, 256>>>(x);
    kB<<<NTHR4 / 128, 128>>>((float*)d_out);
}

// round 5
// speedup vs baseline: 1.1974x; 1.1974x over previous
#include <cuda_runtime.h>
#include <stdint.h>

#define NPIX  200704        // 64 * 56 * 56
#define HW    3136          // 56 * 56
#define WID   56
#define NTHR4 (NPIX / 4)    // 50176 threads, 4 pixels each

// Intermediate: 32 sign bits (channels of h) per pixel, layout [b*HW + s]
__device__ uint32_t g_a[NPIX];

// Packed weights + folded BN params
__device__ unsigned long long g_w1b[32];
__device__ float g_inv1[32], g_sh1[32];
__device__ uint32_t g_w2p[96][3];
__device__ float g_inv2[96], g_sh2[96];
__device__ uint32_t g_w3p[96][3];
__device__ float g_inv3[96], g_sh3[96];
__device__ uint32_t g_w4p[64];
__device__ float g_inv4[64], g_sh4[64];

// ---------------------------------------------------------------------------
// Prep: warp-ballot weight packing + BN folding. 1 block, 1024 threads (32 warps).
// Lane c of a warp loads weight for input-channel c; ballot forms the bitmask.
// ---------------------------------------------------------------------------
__global__ __launch_bounds__(1024) void kPrep(
    const float* __restrict__ w1, const float* __restrict__ g1,
    const float* __restrict__ b1, const float* __restrict__ m1,
    const float* __restrict__ v1,
    const float* __restrict__ w2, const float* __restrict__ g2,
    const float* __restrict__ b2, const float* __restrict__ m2,
    const float* __restrict__ v2,
    const float* __restrict__ w3, const float* __restrict__ g3,
    const float* __restrict__ b3, const float* __restrict__ m3,
    const float* __restrict__ v3,
    const float* __restrict__ w4, const float* __restrict__ g4,
    const float* __restrict__ b4, const float* __restrict__ m4,
    const float* __restrict__ v4)
{
    const int t    = threadIdx.x;
    const int wid  = t >> 5;      // 0..31
    const int lane = t & 31;

    // ---- w1: 32 out channels x 64 in channels -> 64-bit masks. Warp wid owns channel wid.
    {
        int o = wid;
        float lo = w1[o * 64 + lane];
        float hi = w1[o * 64 + 32 + lane];
        uint32_t blo = __ballot_sync(0xffffffffu, lo > 0.0f);
        uint32_t bhi = __ballot_sync(0xffffffffu, hi > 0.0f);
        if (lane == 0)
            g_w1b[o] = (unsigned long long)blo | ((unsigned long long)bhi << 32);
    }

    // ---- w2 / w3: 96 out channels x 32 in x 3 taps. Warp wid owns channels wid, wid+32, wid+64.
#pragma unroll
    for (int rep = 0; rep < 3; rep++) {
        int o = wid + rep * 32;
        float a0 = w2[(o * 32 + lane) * 3 + 0];
        float a1 = w2[(o * 32 + lane) * 3 + 1];
        float a2 = w2[(o * 32 + lane) * 3 + 2];
        float c0 = w3[(o * 32 + lane) * 3 + 0];
        float c1 = w3[(o * 32 + lane) * 3 + 1];
        float c2 = w3[(o * 32 + lane) * 3 + 2];
        uint32_t p0 = __ballot_sync(0xffffffffu, a0 > 0.0f);
        uint32_t p1 = __ballot_sync(0xffffffffu, a1 > 0.0f);
        uint32_t p2 = __ballot_sync(0xffffffffu, a2 > 0.0f);
        uint32_t q0 = __ballot_sync(0xffffffffu, c0 > 0.0f);
        uint32_t q1 = __ballot_sync(0xffffffffu, c1 > 0.0f);
        uint32_t q2 = __ballot_sync(0xffffffffu, c2 > 0.0f);
        if (lane == 0) {
            g_w2p[o][0] = p0; g_w2p[o][1] = p1; g_w2p[o][2] = p2;
            g_w3p[o][0] = q0; g_w3p[o][1] = q1; g_w3p[o][2] = q2;
        }
    }

    // ---- w4: 64 out channels x 32 in. Warp wid owns channels wid, wid+32.
#pragma unroll
    for (int rep = 0; rep < 2; rep++) {
        int o = wid + rep * 32;
        float a = w4[o * 32 + lane];
        uint32_t p = __ballot_sync(0xffffffffu, a > 0.0f);
        if (lane == 0) g_w4p[o] = p;
    }

    // ---- BN folding (per-thread, coalesced loads)
    if (t < 32) {
        float inv = g1[t] * rsqrtf(v1[t] + 1e-5f);
        g_inv1[t] = inv;
        g_sh1[t]  = b1[t] - m1[t] * inv;
    }
    if (t < 96) {
        float inv = g2[t] * rsqrtf(v2[t] + 1e-5f);
        g_inv2[t] = inv; g_sh2[t] = b2[t] - m2[t] * inv;
        inv = g3[t] * rsqrtf(v3[t] + 1e-5f);
        g_inv3[t] = inv; g_sh3[t] = b3[t] - m3[t] * inv;
    }
    if (t < 64) {
        float inv = g4[t] * rsqrtf(v4[t] + 1e-5f);
        g_inv4[t] = inv; g_sh4[t] = b4[t] - m4[t] * inv;
    }
}

// ---------------------------------------------------------------------------
// Kernel A: x [N=64, C=64, 56, 56] (NCHW) -> g_a sign masks
// Each thread: 4 consecutive pixels within one batch image (float4 per channel).
// ---------------------------------------------------------------------------
__global__ __launch_bounds__(256) void kA(const float* __restrict__ x)
{
    __shared__ unsigned long long sw1[32];
    __shared__ float sinv[32], ssh[32];
    if (threadIdx.x < 32) {
        sw1[threadIdx.x]  = g_w1b[threadIdx.x];
        sinv[threadIdx.x] = g_inv1[threadIdx.x];
        ssh[threadIdx.x]  = g_sh1[threadIdx.x];
    }
    __syncthreads();

    int t = blockIdx.x * 256 + threadIdx.x;
    if (t >= NTHR4) return;
    int p = t * 4;                 // global pixel index = b*HW + s
    int b = p / HW;
    int s = p - b * HW;            // multiple of 4 (HW % 4 == 0)
    const float* xb = x + (size_t)b * 64 * HW + s;

    unsigned long long xb0 = 0, xb1 = 0, xb2 = 0, xb3 = 0;
#pragma unroll
    for (int c = 0; c < 64; c++) {
        float4 v = __ldg((const float4*)(xb + (size_t)c * HW));
        unsigned long long m = 1ull << c;
        if (v.x > 0.0f) xb0 |= m;
        if (v.y > 0.0f) xb1 |= m;
        if (v.z > 0.0f) xb2 |= m;
        if (v.w > 0.0f) xb3 |= m;
    }

    uint32_t a0 = 0, a1 = 0, a2 = 0, a3 = 0;
#pragma unroll
    for (int o = 0; o < 32; o++) {
        unsigned long long wb = sw1[o];
        float inv = sinv[o], sh = ssh[o];
        uint32_t m = 1u << o;
        int d0 = 64 - 2 * __popcll(xb0 ^ wb);
        int d1 = 64 - 2 * __popcll(xb1 ^ wb);
        int d2 = 64 - 2 * __popcll(xb2 ^ wb);
        int d3 = 64 - 2 * __popcll(xb3 ^ wb);
        if (fmaf((float)d0, inv, sh) > 0.0f) a0 |= m;
        if (fmaf((float)d1, inv, sh) > 0.0f) a1 |= m;
        if (fmaf((float)d2, inv, sh) > 0.0f) a2 |= m;
        if (fmaf((float)d3, inv, sh) > 0.0f) a3 |= m;
    }
    *(uint4*)(g_a + p) = make_uint4(a0, a1, a2, a3);
}

// ---------------------------------------------------------------------------
// Kernel B: g_a -> output [64,256,56,56]
// Each thread: 4 consecutive pixels along W, all 256 out channels.
// ---------------------------------------------------------------------------
__global__ __launch_bounds__(128) void kB(float* __restrict__ out)
{
    __shared__ uint32_t sw2[96 * 3], sw3[96 * 3], sw4[64];
    __shared__ float si2[96], ss2[96], si3[96], ss3[96], si4[64], ss4[64];

    for (int i = threadIdx.x; i < 96; i += 128) {
        sw2[3 * i]     = g_w2p[i][0];
        sw2[3 * i + 1] = g_w2p[i][1];
        sw2[3 * i + 2] = g_w2p[i][2];
        sw3[3 * i]     = g_w3p[i][0];
        sw3[3 * i + 1] = g_w3p[i][1];
        sw3[3 * i + 2] = g_w3p[i][2];
        si2[i] = g_inv2[i]; ss2[i] = g_sh2[i];
        si3[i] = g_inv3[i]; ss3[i] = g_sh3[i];
    }
    for (int i = threadIdx.x; i < 64; i += 128) {
        sw4[i] = g_w4p[i]; si4[i] = g_inv4[i]; ss4[i] = g_sh4[i];
    }
    __syncthreads();

    int q  = blockIdx.x * 128 + threadIdx.x;   // 0..50175
    int xq = q % 14;
    int r  = q / 14;
    int y  = r % 56;
    int bb = r / 56;
    int base = bb * HW + y * WID;
    int x0   = xq * 4;

    uint4 A0 = *(const uint4*)&g_a[base + x0];
    uint4 Am = make_uint4(0, 0, 0, 0), Ap = make_uint4(0, 0, 0, 0);
    if (y > 0)  Am = *(const uint4*)&g_a[base - WID + x0];
    if (y < 55) Ap = *(const uint4*)&g_a[base + WID + x0];
    uint32_t hL = (xq > 0)  ? g_a[base + x0 - 1] : 0u;
    uint32_t hR = (xq < 13) ? g_a[base + x0 + 4] : 0u;

    int pc0 = __popc(A0.x), pc1 = __popc(A0.y), pc2 = __popc(A0.z), pc3 = __popc(A0.w);
    int pv0 = __popc(Am.x) + pc0 + __popc(Ap.x);
    int pv1 = __popc(Am.y) + pc1 + __popc(Ap.y);
    int pv2 = __popc(Am.z) + pc2 + __popc(Ap.z);
    int pv3 = __popc(Am.w) + pc3 + __popc(Ap.w);
    int pL = __popc(hL), pR = __popc(hR);
    int ph0 = pL  + pc0 + pc1;
    int ph1 = pc0 + pc1 + pc2;
    int ph2 = pc1 + pc2 + pc3;
    int ph3 = pc2 + pc3 + pR;

    float* o1 = out + (size_t)bb * 256 * HW + y * WID + x0;

    // Branch 1: 3x1 vertical conv (channels 0..95)
#pragma unroll 4
    for (int o = 0; o < 96; o++) {
        uint32_t w0 = sw2[3 * o], w1 = sw2[3 * o + 1], w2 = sw2[3 * o + 2];
        float inv = si2[o], sh = ss2[o];
        float4 rv;
        int d;
        d = 2 * (__popc(Am.x & w0) + __popc(A0.x & w1) + __popc(Ap.x & w2)) - pv0;
        rv.x = fmaxf(fmaf((float)d, inv, sh), 0.0f);
        d = 2 * (__popc(Am.y & w0) + __popc(A0.y & w1) + __popc(Ap.y & w2)) - pv1;
        rv.y = fmaxf(fmaf((float)d, inv, sh), 0.0f);
        d = 2 * (__popc(Am.z & w0) + __popc(A0.z & w1) + __popc(Ap.z & w2)) - pv2;
        rv.z = fmaxf(fmaf((float)d, inv, sh), 0.0f);
        d = 2 * (__popc(Am.w & w0) + __popc(A0.w & w1) + __popc(Ap.w & w2)) - pv3;
        rv.w = fmaxf(fmaf((float)d, inv, sh), 0.0f);
        *(float4*)(o1 + (size_t)o * HW) = rv;
    }

    // Branch 2: 1x3 horizontal conv (channels 96..191)
    float* o2 = o1 + (size_t)96 * HW;
#pragma unroll 4
    for (int o = 0; o < 96; o++) {
        uint32_t w0 = sw3[3 * o], w1 = sw3[3 * o + 1], w2 = sw3[3 * o + 2];
        float inv = si3[o], sh = ss3[o];
        float4 rv;
        int d;
        d = 2 * (__popc(hL   & w0) + __popc(A0.x & w1) + __popc(A0.y & w2)) - ph0;
        rv.x = fmaxf(fmaf((float)d, inv, sh), 0.0f);
        d = 2 * (__popc(A0.x & w0) + __popc(A0.y & w1) + __popc(A0.z & w2)) - ph1;
        rv.y = fmaxf(fmaf((float)d, inv, sh), 0.0f);
        d = 2 * (__popc(A0.y & w0) + __popc(A0.z & w1) + __popc(A0.w & w2)) - ph2;
        rv.z = fmaxf(fmaf((float)d, inv, sh), 0.0f);
        d = 2 * (__popc(A0.z & w0) + __popc(A0.w & w1) + __popc(hR   & w2)) - ph3;
        rv.w = fmaxf(fmaf((float)d, inv, sh), 0.0f);
        *(float4*)(o2 + (size_t)o * HW) = rv;
    }

    // Branch 3: 1x1 conv (channels 192..255)
    float* o3 = o1 + (size_t)192 * HW;
#pragma unroll 4
    for (int o = 0; o < 64; o++) {
        uint32_t w = sw4[o];
        float inv = si4[o], sh = ss4[o];
        float4 rv;
        rv.x = fmaxf(fmaf((float)(2 * __popc(A0.x & w) - pc0), inv, sh), 0.0f);
        rv.y = fmaxf(fmaf((float)(2 * __popc(A0.y & w) - pc1), inv, sh), 0.0f);
        rv.z = fmaxf(fmaf((float)(2 * __popc(A0.z & w) - pc2), inv, sh), 0.0f);
        rv.w = fmaxf(fmaf((float)(2 * __popc(A0.w & w) - pc3), inv, sh), 0.0f);
        *(float4*)(o3 + (size_t)o * HW) = rv;
    }
}

// ---------------------------------------------------------------------------
extern "C" void kernel_launch(void* const* d_in, const int* in_sizes, int n_in,
                              void* d_out, int out_size)
{
    const float* x = (const float*)d_in[0];
    kPrep<<<1, 1024>>>((const float*)d_in[1],  (const float*)d_in[2],
                       (const float*)d_in[3],  (const float*)d_in[4],
                       (const float*)d_in[5],
                       (const float*)d_in[6],  (const float*)d_in[7],
                       (const float*)d_in[8],  (const float*)d_in[9],
                       (const float*)d_in[10],
                       (const float*)d_in[11], (const float*)d_in[12],
                       (const float*)d_in[13], (const float*)d_in[14],
                       (const float*)d_in[15],
                       (const float*)d_in[16], (const float*)d_in[17],
                       (const float*)d_in[18], (const float*)d_in[19],
                       (const float*)d_in[20]);
    kA<<<NTHR4 / 256, 256>>>(x);
    kB<<<NTHR4 / 128, 128>>>((float*)d_out);
}